// round 15
// baseline (speedup 1.0000x reference)
#include <cuda_runtime.h>
#include <cuda_bf16.h>

#define FULL 0xffffffffu
typedef unsigned long long u64;

// ---------- packed f32x2 helpers (SASS FFMA2 path, PTX-only) ----------
__device__ __forceinline__ u64 pack2(float x, float y) {
    u64 r; asm("mov.b64 %0, {%1, %2};" : "=l"(r) : "f"(x), "f"(y)); return r;
}
__device__ __forceinline__ float2 unpack2(u64 v) {
    float2 f; asm("mov.b64 {%0, %1}, %2;" : "=f"(f.x), "=f"(f.y) : "l"(v)); return f;
}
__device__ __forceinline__ u64 mul2(u64 a, u64 b) {
    u64 d; asm("mul.rn.f32x2 %0, %1, %2;" : "=l"(d) : "l"(a), "l"(b)); return d;
}
__device__ __forceinline__ u64 fma2(u64 a, u64 b, u64 c) {
    u64 d; asm("fma.rn.f32x2 %0, %1, %2, %3;" : "=l"(d) : "l"(a), "l"(b), "l"(c)); return d;
}

// Layout: 16 lanes per state, 2 states per warp, 16 packed amps per thread.
// d = r*16 + sub, r = 0..15 in registers, sub = lane & 15.
// Wire i acts on d-bit (7-i):
//   wires 0..3 -> r bits 3..0    (in-register butterflies, pb = 8,4,2,1)
//   wires 4..7 -> sub bits 3..0  (cross-lane shfl_xor masks 8,4,2,1; stays in group)
// Pair rule (bit=0 elem a, bit=1 elem b): a' = c*a - s*b ; b' = s*a + c*b.
__device__ __forceinline__ void apply_layer(u64 a[16], const float2* cs, int sub) {
    // in-register wires 0..3
#pragma unroll
    for (int q = 0; q < 4; q++) {
        float2 p = cs[q];
        u64 c2  = pack2(p.x,  p.x);
        u64 s2  = pack2(p.y,  p.y);
        u64 ns2 = pack2(-p.y, -p.y);
        int pb = 1 << (3 - q);
#pragma unroll
        for (int r = 0; r < 16; r++) {
            if (r & pb) continue;
            int r2 = r | pb;
            u64 t  = mul2(ns2, a[r2]);
            u64 u  = mul2(s2,  a[r]);
            u64 nr = fma2(c2, a[r],  t);
            a[r2]  = fma2(c2, a[r2], u);
            a[r]   = nr;
        }
    }
    // cross-lane wires 4..7 (sub bit 7-q -> shfl mask 8,4,2,1)
#pragma unroll
    for (int q = 4; q < 8; q++) {
        float2 p = cs[q];
        int mask = 1 << (7 - q);
        u64 c2 = pack2(p.x, p.x);
        float ss = (sub & mask) ? p.y : -p.y;  // bit0: c*mine - s*other ; bit1: +s*other
        u64 ss2 = pack2(ss, ss);
#pragma unroll
        for (int r = 0; r < 16; r++) {
            float2 f = unpack2(a[r]);
            float ox = __shfl_xor_sync(FULL, f.x, mask);
            float oy = __shfl_xor_sync(FULL, f.y, mask);
            a[r] = fma2(c2, a[r], mul2(ss2, pack2(ox, oy)));
        }
    }
}

// Single fused kernel. 512 threads = 16 warps = 32 states per block.
// Per-block table build costs ONE __sincosf per thread (512 entries / 512
// threads), amortized over 32 states -> ~0.3us aggregate, vs the ~2.9us
// serialized setup-kernel launch it replaces.
// __launch_bounds__(512,2): regcap = 65536/1024 = 64, same proven budget as
// the best kernel; 32 resident warps/SM (occ cap 50%).
__global__ __launch_bounds__(512, 2)
void vqc_fused(const float* __restrict__ x,
               const float* __restrict__ ry1,  const float* __restrict__ crz1,
               const float* __restrict__ ry2,  const float* __restrict__ crz2,
               float* __restrict__ out, int nstates) {
    __shared__ u64        s_d1[256];   // packed (cos,sin) of CRZ1 phase, idx r*16+sub
    __shared__ ulonglong2 s_d2[256];   // {(c,s), (-s,c)} of CRZ2 phase
    __shared__ float2     s_cs1[8], s_cs2[8];

    int tid  = threadIdx.x;
    int warp = blockIdx.x * 16 + (tid >> 5);
    int lane = tid & 31;
    int sub  = lane & 15;
    int gsel = (lane >> 4) << 3;     // 0 for group 0, 8 for group 1
    bool active = (warp * 2 < nstates);

    // ---- table build: warps 0-7 -> diag1, warps 8-15 -> diag2 ----
    // bits[d, i] = (d >> (7-i)) & 1  (wire i <-> bit 7-i of basis index d)
    {
        int d = tid & 255;
        const float* crz = (tid < 256) ? crz1 : crz2;
        int rot = (tid < 256) ? 1 : 7;            // tgt = (i + rot) & 7
        float e = 0.f;
#pragma unroll
        for (int i = 0; i < 8; i++) {
            float bc = (float)((d >> (7 - i)) & 1);
            int   tg = (i + rot) & 7;
            float bt = (float)((d >> (7 - tg)) & 1);
            e += bc * (bt - 0.5f) * crz[i];
        }
        float s, c;
        __sincosf(e, &s, &c);
        if (tid < 256) {
            s_d1[d] = pack2(c, s);
        } else {
            ulonglong2 d2;
            d2.x = pack2(c, s);
            d2.y = pack2(-s, c);
            s_d2[d] = d2;
        }
        if (tid < 8) {
            float ss, cc;
            __sincosf(0.5f * ry1[tid], &ss, &cc);
            s_cs1[tid] = make_float2(cc, ss);
        } else if (tid < 16) {
            float ss, cc;
            __sincosf(0.5f * ry2[tid - 8], &ss, &cc);
            s_cs2[tid - 8] = make_float2(cc, ss);
        }
    }

    // ---- encoder prologue (table-independent; hides MUFU latency pre-bar) ----
    float plane = 0.f, f01[4], f23[4];
    if (active) {
        float xv = x[warp * 16 + sub];   // sub -> (state = sub>>3, wire = sub&7)
        float s0, c0;
        __sincosf(0.5f * xv, &s0, &c0);
        float cw, sw;
        // wires 4..7 -> plane scalar (sub bits 3..0)
        cw = __shfl_sync(FULL, c0, gsel | 4); sw = __shfl_sync(FULL, s0, gsel | 4);
        plane = (sub & 8) ? sw : cw;
        cw = __shfl_sync(FULL, c0, gsel | 5); sw = __shfl_sync(FULL, s0, gsel | 5);
        plane *= (sub & 4) ? sw : cw;
        cw = __shfl_sync(FULL, c0, gsel | 6); sw = __shfl_sync(FULL, s0, gsel | 6);
        plane *= (sub & 2) ? sw : cw;
        cw = __shfl_sync(FULL, c0, gsel | 7); sw = __shfl_sync(FULL, s0, gsel | 7);
        plane *= (sub & 1) ? sw : cw;
        // wires 0,1 -> f01[4] (fold plane), wires 2,3 -> f23[4]
        cw = __shfl_sync(FULL, c0, gsel | 0); sw = __shfl_sync(FULL, s0, gsel | 0);
        float t0c = cw * plane, t0s = sw * plane;
        cw = __shfl_sync(FULL, c0, gsel | 1); sw = __shfl_sync(FULL, s0, gsel | 1);
        f01[0] = t0c * cw; f01[1] = t0c * sw; f01[2] = t0s * cw; f01[3] = t0s * sw;
        cw = __shfl_sync(FULL, c0, gsel | 2); sw = __shfl_sync(FULL, s0, gsel | 2);
        float u0c = cw, u0s = sw;
        cw = __shfl_sync(FULL, c0, gsel | 3); sw = __shfl_sync(FULL, s0, gsel | 3);
        f23[0] = u0c * cw; f23[1] = u0c * sw; f23[2] = u0s * cw; f23[3] = u0s * sw;
    }

    __syncthreads();
    if (!active) return;

    // ---- initial product state, fused with diag1 ----
    // amp(d) = prod_i (bit(7-i,d) ? sin(x_i/2) : cos(x_i/2))
    u64 a[16];
#pragma unroll
    for (int r = 0; r < 16; r++) {
        float amp = f01[r >> 2] * f23[r & 3];
        a[r] = mul2(pack2(amp, amp), s_d1[r * 16 + sub]);
    }

    // ---- RY1 layer ----
    apply_layer(a, s_cs1, sub);

    // ---- diag2: complex multiply, packed: res = (x,x)*(c,s) + (y,y)*(-s,c) ----
#pragma unroll
    for (int r = 0; r < 16; r++) {
        float2 f = unpack2(a[r]);
        ulonglong2 d2 = s_d2[r * 16 + sub];
        a[r] = fma2(pack2(f.x, f.x), d2.x,
                    mul2(pack2(f.y, f.y), d2.y));
    }

    // ---- RY2 layer ----
    apply_layer(a, s_cs2, sub);

    // ---- measurement: out[w] = sum_d (1 - 2*bit(7-w,d)) * |psi_d|^2 ----
    float p[16];
#pragma unroll
    for (int r = 0; r < 16; r++) {
        float2 f = unpack2(a[r]);
        p[r] = f.x * f.x + f.y * f.y;
    }
    // tree over r bits: bit0<->wire3, bit1<->wire2, bit2<->wire1, bit3<->wire0
    float o0, o1 = 0.f, o2 = 0.f, o3 = 0.f, T;
    float l1[8];
#pragma unroll
    for (int i = 0; i < 8; i++) { l1[i] = p[2*i] + p[2*i+1];  o3 += p[2*i] - p[2*i+1]; }
    float l2[4];
#pragma unroll
    for (int i = 0; i < 4; i++) { l2[i] = l1[2*i] + l1[2*i+1]; o2 += l1[2*i] - l1[2*i+1]; }
    float l3[2];
#pragma unroll
    for (int i = 0; i < 2; i++) { l3[i] = l2[2*i] + l2[2*i+1]; o1 += l2[2*i] - l2[2*i+1]; }
    o0 = l3[0] - l3[1];
    T  = l3[0] + l3[1];

    // sum o0..o3 across the 16 lanes of the group (masks stay in group)
#pragma unroll
    for (int m = 1; m < 16; m <<= 1) {
        o0 += __shfl_xor_sync(FULL, o0, m);
        o1 += __shfl_xor_sync(FULL, o1, m);
        o2 += __shfl_xor_sync(FULL, o2, m);
        o3 += __shfl_xor_sync(FULL, o3, m);
    }
    // signed Walsh butterfly on T over the 4 sub bits:
    // lane with sub = 1<<q holds wire (7-q)'s expectation
    float h = T;
#pragma unroll
    for (int q = 0; q < 4; q++) {
        float o = __shfl_xor_sync(FULL, h, 1 << q);
        h = (lane & (1 << q)) ? (o - h) : (h + o);
    }
    int gb = lane & 16;
    float v4 = __shfl_sync(FULL, h, gb | 8);
    float v5 = __shfl_sync(FULL, h, gb | 4);
    float v6 = __shfl_sync(FULL, h, gb | 2);
    float v7 = __shfl_sync(FULL, h, gb | 1);

    if (sub < 8) {
        float v;
        switch (sub) {
            case 0: v = o0; break;
            case 1: v = o1; break;
            case 2: v = o2; break;
            case 3: v = o3; break;
            case 4: v = v4; break;
            case 5: v = v5; break;
            case 6: v = v6; break;
            default: v = v7; break;
        }
        // (state = lane>>4, wire = sub) -> contiguous 16 floats per warp
        out[warp * 16 + gsel + sub] = v;
    }
}

extern "C" void kernel_launch(void* const* d_in, const int* in_sizes, int n_in,
                              void* d_out, int out_size) {
    const float* x    = (const float*)d_in[0];  // input_features (4,4096,8)
    const float* ry1  = (const float*)d_in[1];  // params_ry1 (1,8)
    const float* crz1 = (const float*)d_in[2];  // params_crz1 (1,8)
    const float* ry2  = (const float*)d_in[3];  // params_ry2 (1,8)
    const float* crz2 = (const float*)d_in[4];  // params_crz2 (1,8)
    float* out = (float*)d_out;

    int nstates = in_sizes[0] / 8;              // 16384

    // 32 states per block (16 warps x 2), single fused launch
    int blocks = (nstates + 31) / 32;           // 512
    vqc_fused<<<blocks, 512>>>(x, ry1, crz1, ry2, crz2, out, nstates);
}

// round 17
// speedup vs baseline: 1.1803x; 1.1803x over previous
#include <cuda_runtime.h>
#include <cuda_bf16.h>

#define FULL 0xffffffffu
typedef unsigned long long u64;

// ---------- packed f32x2 helpers (SASS FFMA2 path, PTX-only) ----------
__device__ __forceinline__ u64 pack2(float x, float y) {
    u64 r; asm("mov.b64 %0, {%1, %2};" : "=l"(r) : "f"(x), "f"(y)); return r;
}
__device__ __forceinline__ float2 unpack2(u64 v) {
    float2 f; asm("mov.b64 {%0, %1}, %2;" : "=f"(f.x), "=f"(f.y) : "l"(v)); return f;
}
__device__ __forceinline__ u64 mul2(u64 a, u64 b) {
    u64 d; asm("mul.rn.f32x2 %0, %1, %2;" : "=l"(d) : "l"(a), "l"(b)); return d;
}
__device__ __forceinline__ u64 fma2(u64 a, u64 b, u64 c) {
    u64 d; asm("fma.rn.f32x2 %0, %1, %2, %3;" : "=l"(d) : "l"(a), "l"(b), "l"(c)); return d;
}

// Layout: 16 lanes per state, 2 states per warp, 16 packed amps per thread.
// d = r*16 + sub, r = 0..15 in registers, sub = lane & 15.
// Wire i acts on d-bit (7-i):
//   wires 0..3 -> r bits 3..0    (in-register butterflies, pb = 8,4,2,1)
//   wires 4..7 -> sub bits 3..0  (cross-lane shfl_xor masks 8,4,2,1; stays in group)
// Pair rule (bit=0 elem a, bit=1 elem b): a' = c*a - s*b ; b' = s*a + c*b.
__device__ __forceinline__ void apply_layer(u64 a[16], const float2* cs, int sub) {
    // in-register wires 0..3
#pragma unroll
    for (int q = 0; q < 4; q++) {
        float2 p = cs[q];
        u64 c2  = pack2(p.x,  p.x);
        u64 s2  = pack2(p.y,  p.y);
        u64 ns2 = pack2(-p.y, -p.y);
        int pb = 1 << (3 - q);
#pragma unroll
        for (int r = 0; r < 16; r++) {
            if (r & pb) continue;
            int r2 = r | pb;
            u64 t  = mul2(ns2, a[r2]);
            u64 u  = mul2(s2,  a[r]);
            u64 nr = fma2(c2, a[r],  t);
            a[r2]  = fma2(c2, a[r2], u);
            a[r]   = nr;
        }
    }
    // cross-lane wires 4..7 (sub bit 7-q -> shfl mask 8,4,2,1)
#pragma unroll
    for (int q = 4; q < 8; q++) {
        float2 p = cs[q];
        int mask = 1 << (7 - q);
        u64 c2 = pack2(p.x, p.x);
        float ss = (sub & mask) ? p.y : -p.y;  // bit0: c*mine - s*other ; bit1: +s*other
        u64 ss2 = pack2(ss, ss);
#pragma unroll
        for (int r = 0; r < 16; r++) {
            float2 f = unpack2(a[r]);
            float ox = __shfl_xor_sync(FULL, f.x, mask);
            float oy = __shfl_xor_sync(FULL, f.y, mask);
            a[r] = fma2(c2, a[r], mul2(ss2, pack2(ox, oy)));
        }
    }
}

// Single fused kernel. 128 threads = 4 warps = 8 states per block.
// Table build: 4 __sincosf per thread (512 entries / 128 threads), barrier
// couples only 4 warps, 8 blocks/SM -> fine-grained wave transitions.
// __launch_bounds__(128,8): regcap = 65536/1024 = 64 (the proven budget).
__global__ __launch_bounds__(128, 8)
void vqc_fused(const float* __restrict__ x,
               const float* __restrict__ ry1,  const float* __restrict__ crz1,
               const float* __restrict__ ry2,  const float* __restrict__ crz2,
               float* __restrict__ out, int nstates) {
    __shared__ u64        s_d1[256];   // packed (cos,sin) of CRZ1 phase, idx r*16+sub
    __shared__ ulonglong2 s_d2[256];   // {(c,s), (-s,c)} of CRZ2 phase
    __shared__ float2     s_cs1[8], s_cs2[8];

    int tid  = threadIdx.x;
    int warp = blockIdx.x * 4 + (tid >> 5);
    int lane = tid & 31;
    int sub  = lane & 15;
    int gsel = (lane >> 4) << 3;     // 0 for group 0, 8 for group 1
    bool active = (warp * 2 < nstates);

    // ---- table build: 2 entries of d1 + 2 entries of d2 per thread ----
    // bits[d, i] = (d >> (7-i)) & 1  (wire i <-> bit 7-i of basis index d)
#pragma unroll
    for (int e = tid; e < 256; e += 128) {
        float e1 = 0.f;
#pragma unroll
        for (int i = 0; i < 8; i++) {
            float bc = (float)((e >> (7 - i)) & 1);
            int   tg = (i + 1) & 7;
            float bt = (float)((e >> (7 - tg)) & 1);
            e1 += bc * (bt - 0.5f) * crz1[i];
        }
        float s, c;
        __sincosf(e1, &s, &c);
        s_d1[e] = pack2(c, s);
    }
#pragma unroll
    for (int e = tid; e < 256; e += 128) {
        float e2 = 0.f;
#pragma unroll
        for (int i = 0; i < 8; i++) {
            float bc = (float)((e >> (7 - i)) & 1);
            int   tg = (i + 7) & 7;
            float bt = (float)((e >> (7 - tg)) & 1);
            e2 += bc * (bt - 0.5f) * crz2[i];
        }
        float s, c;
        __sincosf(e2, &s, &c);
        ulonglong2 d2;
        d2.x = pack2(c, s);
        d2.y = pack2(-s, c);
        s_d2[e] = d2;
    }
    if (tid < 8) {
        float ss, cc;
        __sincosf(0.5f * ry1[tid], &ss, &cc);
        s_cs1[tid] = make_float2(cc, ss);
    } else if (tid < 16) {
        float ss, cc;
        __sincosf(0.5f * ry2[tid - 8], &ss, &cc);
        s_cs2[tid - 8] = make_float2(cc, ss);
    }

    // ---- encoder prologue (table-independent; hides MUFU latency pre-bar) ----
    float f01[4], f23[4];
    if (active) {
        float xv = x[warp * 16 + sub];   // sub -> (state = sub>>3, wire = sub&7)
        float s0, c0;
        __sincosf(0.5f * xv, &s0, &c0);
        float cw, sw;
        // wires 4..7 -> plane scalar (sub bits 3..0)
        cw = __shfl_sync(FULL, c0, gsel | 4); sw = __shfl_sync(FULL, s0, gsel | 4);
        float plane = (sub & 8) ? sw : cw;
        cw = __shfl_sync(FULL, c0, gsel | 5); sw = __shfl_sync(FULL, s0, gsel | 5);
        plane *= (sub & 4) ? sw : cw;
        cw = __shfl_sync(FULL, c0, gsel | 6); sw = __shfl_sync(FULL, s0, gsel | 6);
        plane *= (sub & 2) ? sw : cw;
        cw = __shfl_sync(FULL, c0, gsel | 7); sw = __shfl_sync(FULL, s0, gsel | 7);
        plane *= (sub & 1) ? sw : cw;
        // wires 0,1 -> f01[4] (fold plane), wires 2,3 -> f23[4]
        cw = __shfl_sync(FULL, c0, gsel | 0); sw = __shfl_sync(FULL, s0, gsel | 0);
        float t0c = cw * plane, t0s = sw * plane;
        cw = __shfl_sync(FULL, c0, gsel | 1); sw = __shfl_sync(FULL, s0, gsel | 1);
        f01[0] = t0c * cw; f01[1] = t0c * sw; f01[2] = t0s * cw; f01[3] = t0s * sw;
        cw = __shfl_sync(FULL, c0, gsel | 2); sw = __shfl_sync(FULL, s0, gsel | 2);
        float u0c = cw, u0s = sw;
        cw = __shfl_sync(FULL, c0, gsel | 3); sw = __shfl_sync(FULL, s0, gsel | 3);
        f23[0] = u0c * cw; f23[1] = u0c * sw; f23[2] = u0s * cw; f23[3] = u0s * sw;
    }

    __syncthreads();
    if (!active) return;

    // ---- initial product state, fused with diag1 ----
    // amp(d) = prod_i (bit(7-i,d) ? sin(x_i/2) : cos(x_i/2))
    u64 a[16];
#pragma unroll
    for (int r = 0; r < 16; r++) {
        float amp = f01[r >> 2] * f23[r & 3];
        a[r] = mul2(pack2(amp, amp), s_d1[r * 16 + sub]);
    }

    // ---- RY1 layer ----
    apply_layer(a, s_cs1, sub);

    // ---- diag2: complex multiply, packed: res = (x,x)*(c,s) + (y,y)*(-s,c) ----
#pragma unroll
    for (int r = 0; r < 16; r++) {
        float2 f = unpack2(a[r]);
        ulonglong2 d2 = s_d2[r * 16 + sub];
        a[r] = fma2(pack2(f.x, f.x), d2.x,
                    mul2(pack2(f.y, f.y), d2.y));
    }

    // ---- RY2 layer ----
    apply_layer(a, s_cs2, sub);

    // ---- measurement: out[w] = sum_d (1 - 2*bit(7-w,d)) * |psi_d|^2 ----
    float p[16];
#pragma unroll
    for (int r = 0; r < 16; r++) {
        float2 f = unpack2(a[r]);
        p[r] = f.x * f.x + f.y * f.y;
    }
    // tree over r bits: bit0<->wire3, bit1<->wire2, bit2<->wire1, bit3<->wire0
    float o0, o1 = 0.f, o2 = 0.f, o3 = 0.f, T;
    float l1[8];
#pragma unroll
    for (int i = 0; i < 8; i++) { l1[i] = p[2*i] + p[2*i+1];  o3 += p[2*i] - p[2*i+1]; }
    float l2[4];
#pragma unroll
    for (int i = 0; i < 4; i++) { l2[i] = l1[2*i] + l1[2*i+1]; o2 += l1[2*i] - l1[2*i+1]; }
    float l3[2];
#pragma unroll
    for (int i = 0; i < 2; i++) { l3[i] = l2[2*i] + l2[2*i+1]; o1 += l2[2*i] - l2[2*i+1]; }
    o0 = l3[0] - l3[1];
    T  = l3[0] + l3[1];

    // sum o0..o3 across the 16 lanes of the group (masks stay in group)
#pragma unroll
    for (int m = 1; m < 16; m <<= 1) {
        o0 += __shfl_xor_sync(FULL, o0, m);
        o1 += __shfl_xor_sync(FULL, o1, m);
        o2 += __shfl_xor_sync(FULL, o2, m);
        o3 += __shfl_xor_sync(FULL, o3, m);
    }
    // signed Walsh butterfly on T over the 4 sub bits:
    // lane with sub = 1<<q holds wire (7-q)'s expectation
    float h = T;
#pragma unroll
    for (int q = 0; q < 4; q++) {
        float o = __shfl_xor_sync(FULL, h, 1 << q);
        h = (lane & (1 << q)) ? (o - h) : (h + o);
    }
    int gb = lane & 16;
    float v4 = __shfl_sync(FULL, h, gb | 8);
    float v5 = __shfl_sync(FULL, h, gb | 4);
    float v6 = __shfl_sync(FULL, h, gb | 2);
    float v7 = __shfl_sync(FULL, h, gb | 1);

    if (sub < 8) {
        float v;
        switch (sub) {
            case 0: v = o0; break;
            case 1: v = o1; break;
            case 2: v = o2; break;
            case 3: v = o3; break;
            case 4: v = v4; break;
            case 5: v = v5; break;
            case 6: v = v6; break;
            default: v = v7; break;
        }
        // (state = lane>>4, wire = sub) -> contiguous 16 floats per warp
        out[warp * 16 + gsel + sub] = v;
    }
}

extern "C" void kernel_launch(void* const* d_in, const int* in_sizes, int n_in,
                              void* d_out, int out_size) {
    const float* x    = (const float*)d_in[0];  // input_features (4,4096,8)
    const float* ry1  = (const float*)d_in[1];  // params_ry1 (1,8)
    const float* crz1 = (const float*)d_in[2];  // params_crz1 (1,8)
    const float* ry2  = (const float*)d_in[3];  // params_ry2 (1,8)
    const float* crz2 = (const float*)d_in[4];  // params_crz2 (1,8)
    float* out = (float*)d_out;

    int nstates = in_sizes[0] / 8;              // 16384

    // 8 states per block (4 warps x 2), single fused launch
    int blocks = (nstates + 7) / 8;             // 2048
    vqc_fused<<<blocks, 128>>>(x, ry1, crz1, ry2, crz2, out, nstates);
}